// round 11
// baseline (speedup 1.0000x reference)
#include <cuda_runtime.h>

// FNNKernelTransform: per-edge MLP(4->128->128->1056) -> (32x33) kernel -> mat@v + bias
// Fused fp32 implementation with packed f32x2 FMA (Blackwell FFMA2).
//
// Strategy:
//   prep kernel : W3 [128,1056] -> W3p [128,1280] (each 33-col i-block zero-padded to 40)
//   fused kernel: per block = 64 edges, 256 threads
//     phase 1: h1 = relu(x@W1+b1); h2 = relu(h1@W2+b2)   (reg-tiled, W2 smem-staged)
//     phase 2: K = h2 @ W3p chunk-by-chunk (160 cols = 4 i-blocks), reg-tiled GEMM
//              with register-prefetch pipelined smem staging; chunk result -> smem,
//              then contract with [v;1] (+ b3) -> out[e, i]

typedef unsigned long long ull;

#define HID        128
#define CH         32
#define DOUT       1056          // 32*33
#define CPAD       40            // padded i-block width
#define WPAD       (CH * CPAD)   // 1280
#define TILE_E     64
#define NTHREADS   256
#define CHUNK      160           // 4 padded i-blocks per chunk
#define NCHUNK     8
#define KT_STRIDE  162
#define H1_STRIDE  130
#define E_TOTAL    262144

// padded + i-block-aligned copy of W3 (built each launch; deterministic)
__device__ float g_W3p[HID * WPAD];

__global__ void prep_w3_kernel(const float* __restrict__ W3) {
    int idx = blockIdx.x * blockDim.x + threadIdx.x;
    if (idx >= HID * WPAD) return;
    int h = idx / WPAD;
    int c = idx % WPAD;
    int i = c / CPAD, j = c % CPAD;
    g_W3p[idx] = (j < CH + 1) ? W3[h * DOUT + i * (CH + 1) + j] : 0.0f;
}

__device__ __forceinline__ ull fma2(ull a, ull b, ull c) {
    ull d;
    asm("fma.rn.f32x2 %0, %1, %2, %3;" : "=l"(d) : "l"(a), "l"(b), "l"(c));
    return d;
}
__device__ __forceinline__ ull pack2(float x, float y) {
    ull d;
    asm("mov.b64 %0, {%1, %2};" : "=l"(d) : "f"(x), "f"(y));
    return d;
}
__device__ __forceinline__ float2 unpack2(ull v) {
    float2 r;
    asm("mov.b64 {%0, %1}, %2;" : "=f"(r.x), "=f"(r.y) : "l"(v));
    return r;
}

__global__ __launch_bounds__(NTHREADS, 2)
void fnn_fused_kernel(const float* __restrict__ pos_i, const float* __restrict__ pos_j,
                      const float* __restrict__ v,
                      const float* __restrict__ W1, const float* __restrict__ b1,
                      const float* __restrict__ W2, const float* __restrict__ b2,
                      const float* __restrict__ b3,
                      float* __restrict__ out) {
    extern __shared__ float smem[];
    float* h2s = smem;                 // [64][128]   = 8192 f  (persistent)
    float* vs  = h2s + TILE_E * HID;   // [64][34]    = 2176 f  (persistent)
    float* ws  = vs + TILE_E * 34;     // [8][160]    = 1280 f  (stage buf; also xs)
    float* kt  = ws + 8 * CHUNK;       // [64][162]   = 10368 f (K chunk; also h1s[64][130])

    const int tid   = threadIdx.x;
    const int ebase = blockIdx.x * TILE_E;
    const int et = tid >> 4;           // 0..15 -> edge group
    const int ct = tid & 15;           // 0..15 -> column group (cols 2*ct + 32*p + {0,1})
    const int e0 = et * 4;

    // ---------------- stage inputs: x (pos_i|pos_j) into ws, v into vs -------------
    {
        int e = tid >> 2, comp = tid & 3;
        float val = (comp < 2) ? pos_i[(ebase + e) * 2 + comp]
                               : pos_j[(ebase + e) * 2 + (comp - 2)];
        ws[e * 4 + comp] = val;
    }
#pragma unroll
    for (int r = 0; r < 8; r++) {
        int idx = tid + NTHREADS * r;          // 0..2047
        int e = idx >> 5, j = idx & 31;
        vs[e * 34 + j] = v[(ebase + e) * CH + j];
    }
    __syncthreads();

    // ---------------- phase 1a: h1 = relu(x @ W1 + b1)  (into kt region) -----------
#pragma unroll 4
    for (int it = 0; it < 32; it++) {
        int idx = it * NTHREADS + tid;         // 0..8191
        int e = idx >> 7, o = idx & 127;
        const float* xe = ws + e * 4;
        float acc = __ldg(b1 + o);
        acc = fmaf(xe[0], __ldg(W1 + o),           acc);
        acc = fmaf(xe[1], __ldg(W1 + HID + o),     acc);
        acc = fmaf(xe[2], __ldg(W1 + 2 * HID + o), acc);
        acc = fmaf(xe[3], __ldg(W1 + 3 * HID + o), acc);
        kt[e * H1_STRIDE + o] = fmaxf(acc, 0.0f);
    }
    __syncthreads();

    // ---------------- phase 1b: h2 = relu(h1 @ W2 + b2) ----------------------------
    ull acc1[4][4];
#pragma unroll
    for (int s = 0; s < 4; s++)
#pragma unroll
        for (int p = 0; p < 4; p++) acc1[s][p] = 0ull;

    float rW2[4];
#pragma unroll
    for (int r = 0; r < 4; r++) rW2[r] = W2[tid + NTHREADS * r];   // k-tile 0

    for (int kt8 = 0; kt8 < 16; kt8++) {
        __syncthreads();                                  // prev tile reads done
#pragma unroll
        for (int r = 0; r < 4; r++) ws[tid + NTHREADS * r] = rW2[r];
        __syncthreads();
        if (kt8 < 15) {                                   // prefetch next tile
#pragma unroll
            for (int r = 0; r < 4; r++)
                rW2[r] = W2[(kt8 + 1) * 1024 + tid + NTHREADS * r];
        }
#pragma unroll
        for (int k = 0; k < 8; k++) {
            int hh = kt8 * 8 + k;
            float a0 = kt[(e0 + 0) * H1_STRIDE + hh];
            float a1 = kt[(e0 + 1) * H1_STRIDE + hh];
            float a2 = kt[(e0 + 2) * H1_STRIDE + hh];
            float a3 = kt[(e0 + 3) * H1_STRIDE + hh];
            ull pa0 = pack2(a0, a0), pa1 = pack2(a1, a1);
            ull pa2 = pack2(a2, a2), pa3 = pack2(a3, a3);
#pragma unroll
            for (int p = 0; p < 4; p++) {
                ull b = *(const ull*)(ws + k * HID + 2 * ct + 32 * p);
                acc1[0][p] = fma2(pa0, b, acc1[0][p]);
                acc1[1][p] = fma2(pa1, b, acc1[1][p]);
                acc1[2][p] = fma2(pa2, b, acc1[2][p]);
                acc1[3][p] = fma2(pa3, b, acc1[3][p]);
            }
        }
    }
    // epilogue: +b2, relu, store h2s
#pragma unroll
    for (int p = 0; p < 4; p++) {
        int o = 2 * ct + 32 * p;
        float bb0 = __ldg(b2 + o), bb1 = __ldg(b2 + o + 1);
#pragma unroll
        for (int s = 0; s < 4; s++) {
            float2 t = unpack2(acc1[s][p]);
            float2 rr = make_float2(fmaxf(t.x + bb0, 0.0f), fmaxf(t.y + bb1, 0.0f));
            *(float2*)(h2s + (e0 + s) * HID + o) = rr;
        }
    }

    // ---------------- phase 2: K = h2 @ W3p, chunked; contract with [v;1] ----------
    const int eC   = tid >> 2;     // contraction: one (edge, i) pair per thread/chunk
    const int iloc = tid & 3;

    float rW3[5];
#pragma unroll
    for (int r = 0; r < 5; r++) {                         // prefetch chunk0/ktile0
        int idx = tid + NTHREADS * r;
        int row = idx / CHUNK, col = idx % CHUNK;
        rW3[r] = g_W3p[row * WPAD + col];
    }

    for (int cc = 0; cc < NCHUNK; cc++) {
        ull acc2[4][5];
#pragma unroll
        for (int s = 0; s < 4; s++)
#pragma unroll
            for (int p = 0; p < 5; p++) acc2[s][p] = 0ull;

        for (int kt8 = 0; kt8 < 16; kt8++) {
            __syncthreads();                              // prev tile reads done
#pragma unroll
            for (int r = 0; r < 5; r++) ws[tid + NTHREADS * r] = rW3[r];
            __syncthreads();
            {                                             // prefetch next tile
                int nkt = kt8 + 1, ncc = cc;
                if (nkt == 16) { nkt = 0; ncc = cc + 1; }
                if (ncc < NCHUNK) {
#pragma unroll
                    for (int r = 0; r < 5; r++) {
                        int idx = tid + NTHREADS * r;
                        int row = idx / CHUNK, col = idx % CHUNK;
                        rW3[r] = g_W3p[(nkt * 8 + row) * WPAD + ncc * CHUNK + col];
                    }
                }
            }
#pragma unroll
            for (int k = 0; k < 8; k++) {
                int hh = kt8 * 8 + k;
                float a0 = h2s[(e0 + 0) * HID + hh];
                float a1 = h2s[(e0 + 1) * HID + hh];
                float a2 = h2s[(e0 + 2) * HID + hh];
                float a3 = h2s[(e0 + 3) * HID + hh];
                ull pa0 = pack2(a0, a0), pa1 = pack2(a1, a1);
                ull pa2 = pack2(a2, a2), pa3 = pack2(a3, a3);
#pragma unroll
                for (int p = 0; p < 5; p++) {
                    ull b = *(const ull*)(ws + k * CHUNK + 2 * ct + 32 * p);
                    acc2[0][p] = fma2(pa0, b, acc2[0][p]);
                    acc2[1][p] = fma2(pa1, b, acc2[1][p]);
                    acc2[2][p] = fma2(pa2, b, acc2[2][p]);
                    acc2[3][p] = fma2(pa3, b, acc2[3][p]);
                }
            }
        }
        __syncthreads();
        // dump K chunk to smem
#pragma unroll
        for (int s = 0; s < 4; s++)
#pragma unroll
            for (int p = 0; p < 5; p++) {
                float2 t = unpack2(acc2[s][p]);
                *(float2*)(kt + (e0 + s) * KT_STRIDE + 2 * ct + 32 * p) = t;
            }
        __syncthreads();
        // contraction: out[e, i] = sum_j (K[e,i,j] + b3[i,j]) * v[e,j]  +  (K[e,i,32] + b3[i,32])
        {
            int i = cc * 4 + iloc;
            const float* krow = kt + eC * KT_STRIDE + iloc * CPAD;
            const float* vrow = vs + eC * 34;
            const float* b3r  = b3 + i * (CH + 1);
            float acc = krow[CH] + __ldg(b3r + CH);
#pragma unroll
            for (int j = 0; j < CH; j++)
                acc = fmaf(krow[j] + __ldg(b3r + j), vrow[j], acc);
            out[(ebase + eC) * CH + i] = acc;
        }
    }
}

#define SMEM_BYTES ((TILE_E * HID + TILE_E * 34 + 8 * CHUNK + TILE_E * KT_STRIDE) * 4)  // 88064

extern "C" void kernel_launch(void* const* d_in, const int* in_sizes, int n_in,
                              void* d_out, int out_size) {
    const float* pos_i = (const float*)d_in[0];
    const float* pos_j = (const float*)d_in[1];
    const float* v     = (const float*)d_in[2];
    const float* W1    = (const float*)d_in[3];
    const float* b1    = (const float*)d_in[4];
    const float* W2    = (const float*)d_in[5];
    const float* b2    = (const float*)d_in[6];
    const float* W3    = (const float*)d_in[7];
    const float* b3    = (const float*)d_in[8];
    float* out = (float*)d_out;

    // build padded/aligned W3 copy (cheap; deterministic every call)
    prep_w3_kernel<<<(HID * WPAD + NTHREADS - 1) / NTHREADS, NTHREADS>>>(W3);

    // 88 KB dynamic smem > 48 KB default: opt in (idempotent, capture-safe)
    cudaFuncSetAttribute(fnn_fused_kernel,
                         cudaFuncAttributeMaxDynamicSharedMemorySize, SMEM_BYTES);

    fnn_fused_kernel<<<E_TOTAL / TILE_E, NTHREADS, SMEM_BYTES>>>(
        pos_i, pos_j, v, W1, b1, W2, b2, b3, out);
}

// round 14
// speedup vs baseline: 2.8604x; 2.8604x over previous
#include <cuda_runtime.h>
#include <cstdint>

// FNNKernelTransform via mma.sync (m16n8k8 tf32) — family-common PTX, no tcgen05.
//
//   b3 is folded into the last GEMM:  A = [h2 | 1 | 0..0] (K=136),
//   B = [W3 ; b3 ; 0..0]  =>  K-chunk = A @ B already includes bias.
//   Epilogue: out[e,i] = sum_j Kchunk[e, i-block col j] * v'[e,j],
//   v' = [v(32), 1.0, 0x7] per edge.
//
//   Smem A/B use a k-interleaved layout (k' = 2*(k%4) + k/4 within each 8-group)
//   so every mma operand fragment is a single conflict-free LDS.64 (stride 136).

#define NT       256
#define TILE_E   128
#define KA       136            // augmented K (128 + 1 ones + 7 pad), also smem stride
#define NCH      8
#define CHN      160            // 4 padded (40-wide) i-blocks per chunk
#define E_TOTAL  262144

// smem float offsets
#define A_OFF    0              // [128][136] = 17408
#define B_OFF    17408          // [160][136] = 21760
#define VS_OFF   39168          // [128][40]  = 5120
#define OS_OFF   44288          // [128][33]  = 4224
#define SMEM_FLOATS 48512
#define SMEM_BYTES  (SMEM_FLOATS * 4)   // 194048

// k-interleave within 8-group: (k, k+4) become adjacent -> LDS.64 fragments
#define ILV(k) ( ((k) & ~7) | (((k) & 3) << 1) | (((k) >> 2) & 1) )

__device__ __align__(16) float g_W2t[128 * KA];          // [n][k'] tf32
__device__ __align__(16) float g_W3t[NCH * CHN * KA];    // [chunk][p][k'] tf32 (+b3 row)

__device__ __forceinline__ uint32_t tf32r(float x) {
    uint32_t u;
    asm("cvt.rn.tf32.f32 %0, %1;" : "=r"(u) : "f"(x));
    return u;
}
__device__ __forceinline__ void mma8(float* d, const uint32_t* a, uint32_t b0, uint32_t b1) {
    asm volatile(
        "mma.sync.aligned.m16n8k8.row.col.f32.tf32.tf32.f32 "
        "{%0,%1,%2,%3}, {%4,%5,%6,%7}, {%8,%9}, {%0,%1,%2,%3};"
        : "+f"(d[0]), "+f"(d[1]), "+f"(d[2]), "+f"(d[3])
        : "r"(a[0]), "r"(a[1]), "r"(a[2]), "r"(a[3]), "r"(b0), "r"(b1));
}

// ------------------------------------------------------------------ prep ----
__global__ void prep_w2(const float* __restrict__ W2) {
    int idx = blockIdx.x * blockDim.x + threadIdx.x;     // 128*136
    if (idx >= 128 * KA) return;
    int n = idx / KA, kk = idx % KA;
    int k = (kk & ~7) + ((kk & 7) >> 1) + 4 * (kk & 1);  // de-interleave
    float val = (k < 128) ? W2[k * 128 + n] : 0.0f;
    g_W2t[idx] = __uint_as_float(tf32r(val));
}
__global__ void prep_w3(const float* __restrict__ W3, const float* __restrict__ b3) {
    int idx = blockIdx.x * blockDim.x + threadIdx.x;     // 8*160*136
    if (idx >= NCH * CHN * KA) return;
    int c   = idx / (CHN * KA);
    int rem = idx - c * (CHN * KA);
    int p = rem / KA, kk = rem % KA;
    int k = (kk & ~7) + ((kk & 7) >> 1) + 4 * (kk & 1);
    int gcol = c * CHN + p;
    int i = gcol / 40, j = gcol % 40;
    float val = 0.0f;
    if (j < 33) {
        if (k < 128)       val = W3[k * 1056 + i * 33 + j];
        else if (k == 128) val = b3[i * 33 + j];
    }
    g_W3t[idx] = __uint_as_float(tf32r(val));
}

// ------------------------------------------------------------------ main ----
__global__ __launch_bounds__(NT, 1)
void fnn_mma_kernel(const float* __restrict__ pos_i, const float* __restrict__ pos_j,
                    const float* __restrict__ v,
                    const float* __restrict__ W1, const float* __restrict__ b1,
                    const float* __restrict__ b2,
                    float* __restrict__ out) {
    extern __shared__ float sm[];
    float* As = sm + A_OFF;
    float* Bs = sm + B_OFF;
    float* vs = sm + VS_OFF;
    float* os = sm + OS_OFF;

    const int tid  = threadIdx.x;
    const int warp = tid >> 5;
    const int lane = tid & 31;
    const int q    = lane >> 2;      // quad id (row within m16 half)
    const int t    = lane & 3;       // thread-in-quad (k / col pairing)
    const int mg   = warp >> 2;      // 0..1 -> 64-row band
    const int ng   = warp & 3;       // 0..3
    const int mbase = mg * 64;
    const int ebase = blockIdx.x * TILE_E;

    // ---- stage v' [128][40]: v, 1.0 at j=32, 0 at j>=33 --------------------
#pragma unroll
    for (int r = 0; r < 20; r++) {
        int idx = tid + NT * r;                  // 5120
        int e = idx / 40, j = idx - e * 40;
        vs[idx] = (j < 32) ? v[(ebase + e) * 32 + j] : (j == 32 ? 1.0f : 0.0f);
    }
    // ---- copy W2t -> Bs (straight) -----------------------------------------
    {
        float4* B4 = (float4*)Bs;
        const float4* s4 = (const float4*)g_W2t;
#pragma unroll
        for (int r = 0; r < 17; r++) B4[tid + NT * r] = s4[tid + NT * r];
    }
    __syncthreads();

    // ---- h1 = relu(x @ W1 + b1) -> As (tf32, interleaved) ------------------
    {
        int e = tid >> 1, half = tid & 1;
        float x0 = pos_i[(ebase + e) * 2];
        float x1 = pos_i[(ebase + e) * 2 + 1];
        float x2 = pos_j[(ebase + e) * 2];
        float x3 = pos_j[(ebase + e) * 2 + 1];
#pragma unroll 8
        for (int oo = 0; oo < 64; oo++) {
            int o = half * 64 + oo;
            float acc = __ldg(b1 + o);
            acc = fmaf(x0, __ldg(W1 + o),       acc);
            acc = fmaf(x1, __ldg(W1 + 128 + o), acc);
            acc = fmaf(x2, __ldg(W1 + 256 + o), acc);
            acc = fmaf(x3, __ldg(W1 + 384 + o), acc);
            As[e * KA + ILV(o)] = __uint_as_float(tf32r(fmaxf(acc, 0.0f)));
        }
        // augmented cols 128..135: 1.0 at kk=128 (k=128), else 0
#pragma unroll
        for (int r = 0; r < 4; r++) {
            int idx = tid + NT * r;              // 1024
            int ee = idx >> 3, kk8 = idx & 7;
            As[ee * KA + 128 + kk8] = (kk8 == 0) ? 1.0f : 0.0f;
        }
    }
    __syncthreads();

    // ---- phase 1: h2 = relu(h1 @ W2 + b2)  (M=128 N=128 K=128) -------------
    {
        float acc1[4][4][4];
#pragma unroll
        for (int mt = 0; mt < 4; mt++)
#pragma unroll
            for (int nt = 0; nt < 4; nt++)
#pragma unroll
                for (int x = 0; x < 4; x++) acc1[mt][nt][x] = 0.0f;
        const int nbase1 = ng * 32;

#pragma unroll 4
        for (int kg = 0; kg < 16; kg++) {
            uint32_t a[4][4];
#pragma unroll
            for (int mt = 0; mt < 4; mt++) {
                int r0 = mbase + mt * 16 + q;
                uint2 a02 = *(const uint2*)(As + r0 * KA + kg * 8 + 2 * t);
                uint2 a13 = *(const uint2*)(As + (r0 + 8) * KA + kg * 8 + 2 * t);
                a[mt][0] = a02.x; a[mt][1] = a13.x; a[mt][2] = a02.y; a[mt][3] = a13.y;
            }
#pragma unroll
            for (int nt = 0; nt < 4; nt++) {
                int n = nbase1 + nt * 8 + q;
                uint2 b01 = *(const uint2*)(Bs + n * KA + kg * 8 + 2 * t);
#pragma unroll
                for (int mt = 0; mt < 4; mt++) mma8(acc1[mt][nt], a[mt], b01.x, b01.y);
            }
        }
        __syncthreads();          // everyone done reading As before overwrite
        // writeback h2 (+b2, relu, tf32) into As, interleaved
#pragma unroll
        for (int mt = 0; mt < 4; mt++) {
#pragma unroll
            for (int nt = 0; nt < 4; nt++) {
                int r0 = mbase + mt * 16 + q;
                int o0 = nbase1 + nt * 8 + 2 * t;
                float bb0 = __ldg(b2 + o0), bb1 = __ldg(b2 + o0 + 1);
                As[r0 * KA + ILV(o0)] =
                    __uint_as_float(tf32r(fmaxf(acc1[mt][nt][0] + bb0, 0.0f)));
                As[r0 * KA + ILV(o0 + 1)] =
                    __uint_as_float(tf32r(fmaxf(acc1[mt][nt][1] + bb1, 0.0f)));
                As[(r0 + 8) * KA + ILV(o0)] =
                    __uint_as_float(tf32r(fmaxf(acc1[mt][nt][2] + bb0, 0.0f)));
                As[(r0 + 8) * KA + ILV(o0 + 1)] =
                    __uint_as_float(tf32r(fmaxf(acc1[mt][nt][3] + bb1, 0.0f)));
            }
        }
    }
    __syncthreads();

    // ---- phase 2: K-chunks = [h2|1] @ [W3;b3], contract with v' ------------
    const int nbase2 = ng * 40;          // this warp's padded i-block in chunk
    for (int c = 0; c < NCH; c++) {
        // stage B chunk (straight copy of pre-laid-out image)
        {
            float4* B4 = (float4*)Bs;
            const float4* w4 = (const float4*)(g_W3t + c * (CHN * KA));
#pragma unroll
            for (int r = 0; r < 21; r++) B4[tid + NT * r] = w4[tid + NT * r];
            if (tid < 64) B4[tid + 21 * NT] = w4[tid + 21 * NT];
        }
        __syncthreads();

        float acc[4][5][4];
#pragma unroll
        for (int mt = 0; mt < 4; mt++)
#pragma unroll
            for (int nt = 0; nt < 5; nt++)
#pragma unroll
                for (int x = 0; x < 4; x++) acc[mt][nt][x] = 0.0f;

#pragma unroll 4
        for (int kg = 0; kg < 17; kg++) {
            uint32_t a[4][4];
#pragma unroll
            for (int mt = 0; mt < 4; mt++) {
                int r0 = mbase + mt * 16 + q;
                uint2 a02 = *(const uint2*)(As + r0 * KA + kg * 8 + 2 * t);
                uint2 a13 = *(const uint2*)(As + (r0 + 8) * KA + kg * 8 + 2 * t);
                a[mt][0] = a02.x; a[mt][1] = a13.x; a[mt][2] = a02.y; a[mt][3] = a13.y;
            }
#pragma unroll
            for (int nt = 0; nt < 5; nt++) {
                int n = nbase2 + nt * 8 + q;
                uint2 b01 = *(const uint2*)(Bs + n * KA + kg * 8 + 2 * t);
#pragma unroll
                for (int mt = 0; mt < 4; mt++) mma8(acc[mt][nt], a[mt], b01.x, b01.y);
            }
        }

        // epilogue: contract fragments with v' (i-block = c*4 + ng)
        const int iblk = c * 4 + ng;
#pragma unroll
        for (int mt = 0; mt < 4; mt++) {
            int e0 = mbase + mt * 16 + q;
            float s0 = 0.0f, s1 = 0.0f;
#pragma unroll
            for (int nt = 0; nt < 5; nt++) {
                int col = nt * 8 + 2 * t;        // col within 40-wide block
                float2 vp0 = *(const float2*)(vs + e0 * 40 + col);
                float2 vp1 = *(const float2*)(vs + (e0 + 8) * 40 + col);
                s0 = fmaf(acc[mt][nt][0], vp0.x, s0);
                s0 = fmaf(acc[mt][nt][1], vp0.y, s0);
                s1 = fmaf(acc[mt][nt][2], vp1.x, s1);
                s1 = fmaf(acc[mt][nt][3], vp1.y, s1);
            }
            s0 += __shfl_xor_sync(0xFFFFFFFFu, s0, 1);
            s0 += __shfl_xor_sync(0xFFFFFFFFu, s0, 2);
            s1 += __shfl_xor_sync(0xFFFFFFFFu, s1, 1);
            s1 += __shfl_xor_sync(0xFFFFFFFFu, s1, 2);
            if (t == 0) {
                os[e0 * 33 + iblk]       = s0;
                os[(e0 + 8) * 33 + iblk] = s1;
            }
        }
        __syncthreads();           // all B reads + os writes done before next chunk
    }

    // ---- coalesced output ---------------------------------------------------
#pragma unroll
    for (int r = 0; r < 16; r++) {
        int idx = tid + NT * r;                 // 4096
        int e = idx >> 5, i = idx & 31;
        out[(ebase + e) * 32 + i] = os[e * 33 + i];
    }
}

extern "C" void kernel_launch(void* const* d_in, const int* in_sizes, int n_in,
                              void* d_out, int out_size) {
    const float* pos_i = (const float*)d_in[0];
    const float* pos_j = (const float*)d_in[1];
    const float* v     = (const float*)d_in[2];
    const float* W1    = (const float*)d_in[3];
    const float* b1    = (const float*)d_in[4];
    const float* W2    = (const float*)d_in[5];
    const float* b2    = (const float*)d_in[6];
    const float* W3    = (const float*)d_in[7];
    const float* b3    = (const float*)d_in[8];
    float* out = (float*)d_out;

    prep_w2<<<(128 * KA + NT - 1) / NT, NT>>>(W2);
    prep_w3<<<(NCH * CHN * KA + NT - 1) / NT, NT>>>(W3, b3);

    cudaFuncSetAttribute(fnn_mma_kernel,
                         cudaFuncAttributeMaxDynamicSharedMemorySize, SMEM_BYTES);
    fnn_mma_kernel<<<E_TOTAL / TILE_E, NT, SMEM_BYTES>>>(
        pos_i, pos_j, v, W1, b1, b2, out);
}